// round 11
// baseline (speedup 1.0000x reference)
#include <cuda_runtime.h>
#include <cuda_fp16.h>

// ---------------- scratch (device globals; no allocation allowed) ----------
#define NMAX  100032
#define ECAP  1664000

__device__ float  g_hf[NMAX * 64];   // gemm1 output, fp32 UNscaled
__device__ __half g_h [NMAX * 64];   // dis-scaled activations, fp16 (gather src)
__device__ __half g_a [NMAX * 64];   // post-aggregation activations, fp16
__device__ float  g_dis[NMAX];
__device__ int    g_cnt[NMAX];       // zero at entry (module init / scan1 re-zero)
__device__ int    g_rptr[NMAX];      // after fill: block-local inclusive prefix
__device__ int    g_col[ECAP];
__device__ int    g_bsum[128];       // exclusive scan of block totals (carry)

// ---------------- mma.sync helpers ------------------------------------------
__device__ __forceinline__ void mma16816(float acc[4], const unsigned a[4],
                                         const unsigned b[2]) {
    asm volatile(
        "mma.sync.aligned.m16n8k16.row.col.f32.f16.f16.f32 "
        "{%0,%1,%2,%3}, {%4,%5,%6,%7}, {%8,%9}, {%0,%1,%2,%3};\n"
        : "+f"(acc[0]), "+f"(acc[1]), "+f"(acc[2]), "+f"(acc[3])
        : "r"(a[0]), "r"(a[1]), "r"(a[2]), "r"(a[3]), "r"(b[0]), "r"(b[1]));
}

__device__ __forceinline__ unsigned pack_hi(float2 f, unsigned& lo) {
    __half hx = __float2half_rn(f.x), hy = __float2half_rn(f.y);
    __half2 l2 = __halves2half2(__float2half_rn(f.x - __half2float(hx)),
                                __float2half_rn(f.y - __half2float(hy)));
    lo = *(unsigned*)&l2;
    __half2 h2 = __halves2half2(hx, hy);
    return *(unsigned*)&h2;
}

// Stage W[K][64] (row-major fp32) into per-thread B-fragment records:
//   sB[(ks*64 + nn)*4 + t] = {bh0, bh1, bl0, bl1}; decomposition of i must
//   match consumer index: t = i&3, nn = (i>>2)&63, ks = i>>8.
template <int K>
__device__ __forceinline__ void stage_B(uint4* sB, const float* __restrict__ W,
                                        int tid) {
    constexpr int ENT = (K / 16) * 64 * 4;
    for (int i = tid; i < ENT; i += 256) {
        int t = i & 3;
        int nn = (i >> 2) & 63;
        int ks = i >> 8;
        int k0 = ks * 16 + t * 2;
        float w0 = W[k0 * 64 + nn],       w1 = W[(k0 + 1) * 64 + nn];
        float w2 = W[(k0 + 8) * 64 + nn], w3 = W[(k0 + 9) * 64 + nn];
        unsigned l01, l23;
        uint4 v;
        v.x = pack_hi(make_float2(w0, w1), l01);
        v.y = pack_hi(make_float2(w2, w3), l23);
        v.z = l01;
        v.w = l23;
        sB[i] = v;
    }
}

// ---------------- FUSED launch 1: hist (even blocks) + gemm1 (odd) ----------
// hist: atomic degree count (latency-bound, issue ~2%).
// gemm1: HF[n,64] = x[n,128] @ W1 (fp32, UNscaled — no dependencies at all).
// Interleaved so every wave holds both; hist's idle slots absorb MMA work.
__global__ void __launch_bounds__(256) k_hist_gemm1(
        const float* __restrict__ Ain, const float* __restrict__ W, int n, int gb,
        const int* __restrict__ dst, int E, int e4b) {
    constexpr int K = 128;
    extern __shared__ __align__(16) uint4 sB[];   // 32 KB

    int mn = (gb < e4b) ? gb : e4b;
    int m2 = 2 * mn;
    bool isHist;
    int id;
    if ((int)blockIdx.x < m2) {
        isHist = (blockIdx.x & 1) == 0;
        id = blockIdx.x >> 1;
    } else {
        isHist = (e4b > gb);
        id = mn + (blockIdx.x - m2);
    }

    if (isHist) {
        if (id >= e4b) return;
        int e = (id * 256 + threadIdx.x) * 4;
        if (e + 4 <= E) {
            int4 d = *(const int4*)(dst + e);
            atomicAdd(&g_cnt[d.x], 1);
            atomicAdd(&g_cnt[d.y], 1);
            atomicAdd(&g_cnt[d.z], 1);
            atomicAdd(&g_cnt[d.w], 1);
        } else {
            for (; e < E; e++) atomicAdd(&g_cnt[dst[e]], 1);
        }
        return;
    }
    if (id >= gb) return;

    // ---------------- gemm1 body (no dis; fp32 out) ----------------
    int tid = threadIdx.x;
    int wid = tid >> 5, lane = tid & 31;
    int wm = wid & 3, wn = wid >> 2;
    int row0 = id * 64;

    stage_B<K>(sB, W, tid);
    __syncthreads();

    float acc[4][4];
#pragma unroll
    for (int f = 0; f < 4; f++)
#pragma unroll
        for (int j = 0; j < 4; j++) acc[f][j] = 0.f;

    int g = lane >> 2, t = lane & 3;
    int r0 = row0 + wm * 16 + g, r1 = r0 + 8;
    bool ok0 = r0 < n, ok1 = r1 < n;
    const float* A0 = Ain + (size_t)r0 * K;
    const float* A1 = Ain + (size_t)r1 * K;
    const float2 z2 = make_float2(0.f, 0.f);

#pragma unroll
    for (int ks = 0; ks < K / 16; ks++) {
        int kk = ks * 16 + t * 2;
        float2 f0 = ok0 ? *(const float2*)(A0 + kk) : z2;
        float2 f1 = ok1 ? *(const float2*)(A1 + kk) : z2;
        float2 f2 = ok0 ? *(const float2*)(A0 + kk + 8) : z2;
        float2 f3 = ok1 ? *(const float2*)(A1 + kk + 8) : z2;
        unsigned ah[4], al[4];
        ah[0] = pack_hi(f0, al[0]);
        ah[1] = pack_hi(f1, al[1]);
        ah[2] = pack_hi(f2, al[2]);
        ah[3] = pack_hi(f3, al[3]);
#pragma unroll
        for (int nf = 0; nf < 4; nf++) {
            int nn = wn * 32 + nf * 8 + g;
            uint4 v = sB[(ks * 64 + nn) * 4 + t];
            unsigned bh[2] = {v.x, v.y}, bl[2] = {v.z, v.w};
            mma16816(acc[nf], ah, bh);
            mma16816(acc[nf], ah, bl);
            mma16816(acc[nf], al, bh);
        }
    }

#pragma unroll
    for (int nf = 0; nf < 4; nf++) {
        int col = wn * 32 + nf * 8 + t * 2;
        if (ok0)
            *(float2*)(g_hf + (size_t)r0 * 64 + col) =
                make_float2(acc[nf][0], acc[nf][1]);
        if (ok1)
            *(float2*)(g_hf + (size_t)r1 * 64 + col) =
                make_float2(acc[nf][2], acc[nf][3]);
    }
}

// ---------------- scans ------------------------------------------------------
__device__ __forceinline__ int blockscan_excl(int v, int* total) {
    __shared__ int ws[32];
    int lane = threadIdx.x & 31, wid = threadIdx.x >> 5;
    int s = v;
#pragma unroll
    for (int o = 1; o < 32; o <<= 1) {
        int t = __shfl_up_sync(0xffffffffu, s, o);
        if (lane >= o) s += t;
    }
    if (lane == 31) ws[wid] = s;
    __syncthreads();
    if (wid == 0) {
        int u = ws[lane];
#pragma unroll
        for (int o = 1; o < 32; o <<= 1) {
            int t = __shfl_up_sync(0xffffffffu, u, o);
            if (lane >= o) u += t;
        }
        ws[lane] = u;
    }
    __syncthreads();
    int incl = s + (wid ? ws[wid - 1] : 0);
    if (total) *total = ws[31];
    return incl - v;
}

// scan of cnt -> rptr (block-local) + block totals; dis = rsqrt(deg+1);
// re-zeroes g_cnt so the NEXT graph replay's hist starts from zero
// (module load zero-inits globals, so the very first call is also correct).
__global__ void k_scan1(int n) {
    int i = blockIdx.x * 1024 + threadIdx.x;
    int v = (i < n) ? g_cnt[i] : 0;
    int tot;
    int ex = blockscan_excl(v, &tot);
    if (i < n) {
        g_rptr[i] = ex;
        g_dis[i] = rsqrtf((float)(v + 1));   // +1 self loop; always > 0
        g_cnt[i] = 0;
    }
    if (threadIdx.x == 0) g_bsum[blockIdx.x] = tot;
}

__global__ void k_scan2(int nb) {
    int i = threadIdx.x;
    int v = (i < nb) ? g_bsum[i] : 0;   // reads complete before writes (barrier in scan)
    int ex = blockscan_excl(v, nullptr);
    if (i < nb) g_bsum[i] = ex;
}

// ---------------- FUSED launch 4: fill + dis-scale --------------------------
// fill (blockIdx%3==0): CSR slot = local post-increment + block carry.
// scale (else): g_h[fp16] = g_hf[fp32] * dis[row] — single rounding, bitwise
// identical to scaling inside the gemm epilogue. Streams under fill's idle slots.
__global__ void __launch_bounds__(256) k_fill_scale(
        const int* __restrict__ src, const int* __restrict__ dst, int E, int NF,
        int n, int NS) {
    int q = blockIdx.x / 3, r = blockIdx.x % 3;
    if (r == 0) {
        if (q >= NF) return;
        int e = (q * 256 + threadIdx.x) * 4;
        if (e + 4 <= E) {
            int4 d = *(const int4*)(dst + e);
            int4 s = *(const int4*)(src + e);
            g_col[atomicAdd(&g_rptr[d.x], 1) + g_bsum[d.x >> 10]] = s.x;
            g_col[atomicAdd(&g_rptr[d.y], 1) + g_bsum[d.y >> 10]] = s.y;
            g_col[atomicAdd(&g_rptr[d.z], 1) + g_bsum[d.z >> 10]] = s.z;
            g_col[atomicAdd(&g_rptr[d.w], 1) + g_bsum[d.w >> 10]] = s.w;
        } else {
            for (; e < E; e++) {
                int d = dst[e];
                g_col[atomicAdd(&g_rptr[d], 1) + g_bsum[d >> 10]] = src[e];
            }
        }
        return;
    }
    int sid = q * 2 + (r - 1);
    if (sid >= NS) return;
    int i8 = sid * 256 + threadIdx.x;        // one 8-element group per thread
    if (i8 >= n * 8) return;
    int row = i8 >> 3;
    float d = g_dis[row];
    const float4* hf = (const float4*)g_hf + (size_t)i8 * 2;
    float4 a = hf[0], b = hf[1];
    __half2 h0 = __floats2half2_rn(a.x * d, a.y * d);
    __half2 h1 = __floats2half2_rn(a.z * d, a.w * d);
    __half2 h2 = __floats2half2_rn(b.x * d, b.y * d);
    __half2 h3 = __floats2half2_rn(b.z * d, b.w * d);
    uint4 o;
    o.x = *(unsigned*)&h0; o.y = *(unsigned*)&h1;
    o.z = *(unsigned*)&h2; o.w = *(unsigned*)&h3;
    *(uint4*)(g_h + (size_t)i8 * 8) = o;
}

// ---------------- GEMM2 via mma.sync ----------------------------------------
__global__ void __launch_bounds__(256) k_gemm2_mma(const float* __restrict__ W, int n) {
    constexpr int K = 64;
    constexpr int LD = K + 8;
    extern __shared__ __align__(16) uint4 dynu[];
    uint4* sB = dynu;                                   // 16 KB
    __half* sAh = (__half*)(dynu + (K / 16) * 64 * 4);  // [64][LD]

    int tid = threadIdx.x;
    int wid = tid >> 5, lane = tid & 31;
    int wm = wid & 3, wn = wid >> 2;
    int row0 = blockIdx.x * 64;

    stage_B<K>(sB, W, tid);
    for (int i = tid; i < 64 * (K / 8); i += 256) {
        int row = i / (K / 8), c8 = i % (K / 8);
        uint4 v = *(const uint4*)(g_a + (size_t)(row0 + row) * K + c8 * 8);
        *(uint4*)(sAh + row * LD + c8 * 8) = v;
    }
    __syncthreads();

    float acc[4][4];
#pragma unroll
    for (int f = 0; f < 4; f++)
#pragma unroll
        for (int j = 0; j < 4; j++) acc[f][j] = 0.f;

    int g = lane >> 2, t = lane & 3;

#pragma unroll
    for (int ks = 0; ks < K / 16; ks++) {
        int kk = ks * 16 + t * 2;
        int r = wm * 16 + g;
        unsigned ah[4];
        ah[0] = *(const unsigned*)(sAh + r * LD + kk);
        ah[1] = *(const unsigned*)(sAh + (r + 8) * LD + kk);
        ah[2] = *(const unsigned*)(sAh + r * LD + kk + 8);
        ah[3] = *(const unsigned*)(sAh + (r + 8) * LD + kk + 8);
#pragma unroll
        for (int nf = 0; nf < 4; nf++) {
            int nn = wn * 32 + nf * 8 + g;
            uint4 v = sB[(ks * 64 + nn) * 4 + t];
            unsigned bh[2] = {v.x, v.y}, bl[2] = {v.z, v.w};
            mma16816(acc[nf], ah, bh);
            mma16816(acc[nf], ah, bl);
        }
    }

    int r0 = row0 + wm * 16 + g, r1 = r0 + 8;
    float d0 = (r0 < n) ? g_dis[r0] : 0.f;
    float d1 = (r1 < n) ? g_dis[r1] : 0.f;
#pragma unroll
    for (int nf = 0; nf < 4; nf++) {
        int col = wn * 32 + nf * 8 + t * 2;
        if (r0 < n)
            *(__half2*)(g_h + (size_t)r0 * 64 + col) =
                __floats2half2_rn(acc[nf][0] * d0, acc[nf][1] * d0);
        if (r1 < n)
            *(__half2*)(g_h + (size_t)r1 * 64 + col) =
                __floats2half2_rn(acc[nf][2] * d1, acc[nf][3] * d1);
    }
}

// ---------------- aggregation: warp per dst node ----------------------------
template <bool FC>
__global__ void __launch_bounds__(256) k_agg(const float* __restrict__ bias,
                                             const float* __restrict__ Wfc,
                                             const float* __restrict__ bfc,
                                             float* __restrict__ out, int n) {
    int w = (blockIdx.x * 256 + threadIdx.x) >> 5;
    int lane = threadIdx.x & 31;
    if (w >= n) return;

    int start = w ? (__ldg(&g_rptr[w - 1]) + __ldg(&g_bsum[(w - 1) >> 10])) : 0;
    int end = __ldg(&g_rptr[w]) + __ldg(&g_bsum[w >> 10]);

    const __half2* __restrict__ H2 = (const __half2*)g_h;
    float2 acc = __half22float2(H2[(size_t)w * 32 + lane]);   // self loop

    int e = start;
    for (; e + 4 <= end; e += 4) {
        int s0 = __ldg(&g_col[e]), s1 = __ldg(&g_col[e + 1]);
        int s2 = __ldg(&g_col[e + 2]), s3 = __ldg(&g_col[e + 3]);
        float2 v0 = __half22float2(H2[(size_t)s0 * 32 + lane]);
        float2 v1 = __half22float2(H2[(size_t)s1 * 32 + lane]);
        float2 v2 = __half22float2(H2[(size_t)s2 * 32 + lane]);
        float2 v3 = __half22float2(H2[(size_t)s3 * 32 + lane]);
        acc.x += (v0.x + v1.x) + (v2.x + v3.x);
        acc.y += (v0.y + v1.y) + (v2.y + v3.y);
    }
    for (; e < end; e++) {
        float2 v = __half22float2(H2[(size_t)__ldg(&g_col[e]) * 32 + lane]);
        acc.x += v.x;
        acc.y += v.y;
    }

    float d = g_dis[w];
    float2 b = ((const float2*)bias)[lane];
    float ox = fmaxf(fmaf(acc.x, d, b.x), 0.f);
    float oy = fmaxf(fmaf(acc.y, d, b.y), 0.f);

    if (!FC) {
        ((__half2*)g_a)[(size_t)w * 32 + lane] = __floats2half2_rn(ox, oy);
    } else {
        const float4* Wf = (const float4*)Wfc;   // [64][4]
        float4 w0 = Wf[2 * lane], w1 = Wf[2 * lane + 1];
        float4 y;
        y.x = ox * w0.x + oy * w1.x;
        y.y = ox * w0.y + oy * w1.y;
        y.z = ox * w0.z + oy * w1.z;
        y.w = ox * w0.w + oy * w1.w;
#pragma unroll
        for (int o = 16; o; o >>= 1) {
            y.x += __shfl_xor_sync(0xffffffffu, y.x, o);
            y.y += __shfl_xor_sync(0xffffffffu, y.y, o);
            y.z += __shfl_xor_sync(0xffffffffu, y.z, o);
            y.w += __shfl_xor_sync(0xffffffffu, y.w, o);
        }
        if (lane == 0) {
            float4 bf = *(const float4*)bfc;
            ((float4*)out)[w] = make_float4(y.x + bf.x, y.y + bf.y, y.z + bf.z, y.w + bf.w);
        }
    }
}

// ---------------- launch ----------------------------------------------------

extern "C" void kernel_launch(void* const* d_in, const int* in_sizes, int n_in,
                              void* d_out, int out_size) {
    const float* x   = (const float*)d_in[0];
    const int*   ei  = (const int*)d_in[1];
    const float* W1  = (const float*)d_in[2];
    const float* b1  = (const float*)d_in[3];
    const float* W2  = (const float*)d_in[4];
    const float* b2  = (const float*)d_in[5];
    const float* Wfc = (const float*)d_in[6];
    const float* bfc = (const float*)d_in[7];

    int n = in_sizes[0] / 128;
    int E = in_sizes[1] / 2;
    if (n > NMAX) n = NMAX;
    if (E > ECAP) E = ECAP;
    const int* src = ei;
    const int* dst = ei + E;
    int nb = (n + 1023) / 1024;
    int e4b = (E / 4 + 256) / 256;
    int gb = (n + 63) / 64;
    int NS = (n * 8 + 255) / 256;                    // scale blocks
    int cmax = (e4b > (NS + 1) / 2) ? e4b : (NS + 1) / 2;

    const int SMF = (128 / 16) * 64 * 4 * 16;                    // 32768
    const int SM2 = (64 / 16) * 64 * 4 * 16 + 64 * (64 + 8) * 2; // 25600
    cudaFuncSetAttribute(k_hist_gemm1,
                         cudaFuncAttributeMaxDynamicSharedMemorySize, SMF);
    cudaFuncSetAttribute(k_gemm2_mma,
                         cudaFuncAttributeMaxDynamicSharedMemorySize, SM2);

    // L1: hist + gemm1 (both dependency-free), role-interleaved
    k_hist_gemm1<<<gb + e4b, 256, SMF>>>(x, W1, n, gb, dst, E, e4b);
    k_scan1<<<nb, 1024>>>(n);
    k_scan2<<<1, 1024>>>(nb);
    // L4: fill + dis-scale, 1:2 interleaved
    k_fill_scale<<<3 * cmax, 256>>>(src, dst, E, e4b, n, NS);

    k_agg<false><<<(n + 7) / 8, 256>>>(b1, nullptr, nullptr, nullptr, n);
    k_gemm2_mma<<<gb, 256, SM2>>>(W2, n);
    k_agg<true><<<(n + 7) / 8, 256>>>(b2, Wfc, bfc, (float*)d_out, n);
}